// round 16
// baseline (speedup 1.0000x reference)
#include <cuda_runtime.h>
#include <cuda_fp16.h>
#include <math.h>
#include <stdint.h>

// Problem constants
#define Bc 2
#define Tc 2048
#define Dc 1024
#define Hc 16
#define DHc 64
#define NBc 32
#define ROWS (Bc*Tc)          // 4096

// ---------------- scratch ----------------
__device__ float    g_h   [ (size_t)ROWS * Dc ];       // row-major (LN out)
__device__ uint32_t g_q   [ (size_t)ROWS * Dc / 2 ];   // Q fp16 A-image [bh][qb][2 slabs][128][16]
__device__ uint32_t g_k   [ (size_t)ROWS * Dc / 2 ];   // K fp16 B-image [bh][kt][2 slabs][64][16]
__device__ uint32_t g_v   [ (size_t)ROWS * Dc / 2 ];   // V fp16 B-image (n=dh, k=key)
__device__ float    g_attn[ (size_t)ROWS * Dc ];       // row-major [B,T,H,DH]
__device__ float    g_x2  [ (size_t)ROWS * Dc ];
__device__ float    g_ffn [ (size_t)ROWS * 4 * Dc ];
// pre-swizzled fp16 weight tiles: [n_tile][k_slab32][2048 half2-units]
__device__ uint32_t g_wq_t[ (size_t)Dc * Dc / 2 ];
__device__ uint32_t g_wk_t[ (size_t)Dc * Dc / 2 ];
__device__ uint32_t g_wv_t[ (size_t)Dc * Dc / 2 ];
__device__ uint32_t g_wo_t[ (size_t)Dc * Dc / 2 ];
__device__ uint32_t g_w1_t[ (size_t)Dc * 4 * Dc / 2 ];
__device__ uint32_t g_w2_t[ (size_t)Dc * 4 * Dc / 2 ];

// ---------------- helpers ----------------
__device__ __forceinline__ uint32_t pack2(float a, float b)
{
    __half2 h = __floats2half2_rn(a, b);
    return *(uint32_t*)&h;
}

// fp16 mma m16n8k16, fp32 accumulate
__device__ __forceinline__ void mma16(float c[4],
    uint32_t a0, uint32_t a1, uint32_t a2, uint32_t a3,
    uint32_t b0, uint32_t b1)
{
    asm volatile(
        "mma.sync.aligned.m16n8k16.row.col.f32.f16.f16.f32 "
        "{%0,%1,%2,%3}, {%4,%5,%6,%7}, {%8,%9}, {%0,%1,%2,%3};"
        : "+f"(c[0]), "+f"(c[1]), "+f"(c[2]), "+f"(c[3])
        : "r"(a0), "r"(a1), "r"(a2), "r"(a3), "r"(b0), "r"(b1));
}

__device__ __forceinline__ void cp_async16(uint32_t smem_dst, const void* gptr)
{
    asm volatile("cp.async.cg.shared.global [%0], [%1], 16;"
                 :: "r"(smem_dst), "l"(gptr));
}
__device__ __forceinline__ void cp_commit()  { asm volatile("cp.async.commit_group;"); }
__device__ __forceinline__ void cp_wait0()   { asm volatile("cp.async.wait_group 0;" ::: "memory"); }

__device__ __forceinline__ float gelu_f(float v)
{
    return 0.5f * v * (1.0f + erff(v * 0.70710678118654752f));
}

// ---------------- weight prep: W[K][N] -> fp16 interleaved B tiles ------------
__global__ void __launch_bounds__(256) prep_all(
    const float* __restrict__ Wq, const float* __restrict__ Wk,
    const float* __restrict__ Wv, const float* __restrict__ Wo,
    const float* __restrict__ W1, const float* __restrict__ W2,
    uint32_t* __restrict__ wq_t, uint32_t* __restrict__ wk_t,
    uint32_t* __restrict__ wv_t, uint32_t* __restrict__ wo_t,
    uint32_t* __restrict__ w1_t, uint32_t* __restrict__ w2_t)
{
    int id = blockIdx.x, tid = threadIdx.x;
    const float* W; uint32_t* out; int N, kslabs, ks, nt;
    if (id < 1024) {
        int m = id >> 8, local = id & 255;
        const float* Ws[4] = {Wq, Wk, Wv, Wo};
        uint32_t* Os[4] = {wq_t, wk_t, wv_t, wo_t};
        W = Ws[m]; out = Os[m]; N = Dc; kslabs = 32;
        ks = local & 31; nt = local >> 5;
    } else if (id < 2048) {
        int local = id - 1024;
        W = W1; out = w1_t; N = 4 * Dc; kslabs = 32;
        ks = local & 31; nt = local >> 5;
    } else {
        int local = id - 2048;
        W = W2; out = w2_t; N = Dc; kslabs = 128;
        ks = local & 127; nt = local >> 7;
    }
    uint32_t* dst = out + ((size_t)nt * kslabs + ks) * 2048;
    const float* Wb = W + (size_t)(ks * 32) * N + nt * 128;
    #pragma unroll
    for (int j = 0; j < 2; j++) {
        int u = tid + 256 * j;
        int n = u & 127, g = u >> 7;
        const float* p = Wb + n;
        float v0 = p[(size_t)(2*g)      * N], v1 = p[(size_t)(2*g + 1)  * N];
        float v2 = p[(size_t)(2*g + 8)  * N], v3 = p[(size_t)(2*g + 9)  * N];
        float v4 = p[(size_t)(2*g + 16) * N], v5 = p[(size_t)(2*g + 17) * N];
        float v6 = p[(size_t)(2*g + 24) * N], v7 = p[(size_t)(2*g + 25) * N];
        uint4 o = make_uint4(pack2(v0, v1), pack2(v2, v3),
                             pack2(v4, v5), pack2(v6, v7));
        *(uint4*)&dst[n * 16 + 4 * ((g + n) & 3)] = o;
    }
}

// ---------------- LayerNorm (row-major out) -----------------------------------
__global__ void __launch_bounds__(256) ln_kernel(const float* __restrict__ x,
                                                 const float* __restrict__ g,
                                                 const float* __restrict__ b,
                                                 float* __restrict__ o)
{
    __shared__ float sred[16];
    int row = blockIdx.x;
    int tid = threadIdx.x;
    const float* xr = x + (size_t)row * Dc;
    float4 v = *(const float4*)&xr[tid * 4];
    float s  = v.x + v.y + v.z + v.w;
    float s2 = v.x*v.x + v.y*v.y + v.z*v.z + v.w*v.w;
    #pragma unroll
    for (int off = 16; off; off >>= 1) {
        s  += __shfl_xor_sync(0xffffffffu, s,  off);
        s2 += __shfl_xor_sync(0xffffffffu, s2, off);
    }
    if ((tid & 31) == 0) { sred[tid >> 5] = s; sred[8 + (tid >> 5)] = s2; }
    __syncthreads();
    float S = 0.f, S2 = 0.f;
    #pragma unroll
    for (int i = 0; i < 8; i++) { S += sred[i]; S2 += sred[8 + i]; }
    float mean = S * (1.0f / Dc);
    float var  = S2 * (1.0f / Dc) - mean * mean;
    float rstd = rsqrtf(var + 1e-5f);
    float4 gv = *(const float4*)&g[tid * 4];
    float4 bv = *(const float4*)&b[tid * 4];
    float4 ov;
    ov.x = (v.x - mean) * rstd * gv.x + bv.x;
    ov.y = (v.y - mean) * rstd * gv.y + bv.y;
    ov.z = (v.z - mean) * rstd * gv.z + bv.z;
    ov.w = (v.w - mean) * rstd * gv.w + bv.w;
    *(float4*)&o[(size_t)row * Dc + tid * 4] = ov;
}

// =====================  fp16 GEMM building blocks (r15-proven) ================
#define GEMM_PROLOGUE()                                                          \
    int tid  = threadIdx.x;                                                      \
    int lane = tid & 31;                                                         \
    int warp = tid >> 5;                                                         \
    int q4 = lane & 3, rr = lane >> 2;                                           \
    int wm = (warp & 1) * 64;                                                    \
    int wn = (warp >> 1) * 32;                                                   \
    int arow = tid >> 1;                                                         \
    int achk = tid & 1;                                                          \
    int ab = arow * 16 + 2 * achk;                                               \
    int ax = arow & 3;                                                           \
    uint32_t sB_u32 = (uint32_t)__cvta_generic_to_shared(&sB[0][0]);             \
    float acc[4][4][4];                                                          \
    _Pragma("unroll") for (int i = 0; i < 4; i++)                                \
        _Pragma("unroll") for (int j = 0; j < 4; j++)                            \
            _Pragma("unroll") for (int r = 0; r < 4; r++) acc[i][j][r] = 0.f;    \
    int frot = 4 * ((q4 + rr) & 3);

#define GEMM_A_STORE(dstbuf, f0, f1, f2, f3)                                     \
    {                                                                            \
        uint32_t u0 = pack2(f0.x, f0.y), u1 = pack2(f0.z, f0.w);                 \
        uint32_t u2 = pack2(f1.x, f1.y), u3 = pack2(f1.z, f1.w);                 \
        uint32_t u4 = pack2(f2.x, f2.y), u5 = pack2(f2.z, f2.w);                 \
        uint32_t u6 = pack2(f3.x, f3.y), u7 = pack2(f3.z, f3.w);                 \
        *(uint2*)&sA[dstbuf][ab + 4 * ((0 + ax) & 3)] = make_uint2(u0, u4);      \
        *(uint2*)&sA[dstbuf][ab + 4 * ((1 + ax) & 3)] = make_uint2(u1, u5);      \
        *(uint2*)&sA[dstbuf][ab + 4 * ((2 + ax) & 3)] = make_uint2(u2, u6);      \
        *(uint2*)&sA[dstbuf][ab + 4 * ((3 + ax) & 3)] = make_uint2(u3, u7);      \
    }

#define GEMM_LOAD_TILE0()                                                        \
    {                                                                            \
        cp_async16(sB_u32 + tid * 32,      BtBase + tid * 8);                    \
        cp_async16(sB_u32 + tid * 32 + 16, BtBase + tid * 8 + 4);                \
        cp_commit();                                                             \
        const float4* Ap4 = (const float4*)Aptr;                                 \
        float4 f0 = Ap4[0], f1 = Ap4[1], f2 = Ap4[2], f3 = Ap4[3];               \
        GEMM_A_STORE(0, f0, f1, f2, f3);                                         \
        cp_wait0();                                                              \
    }                                                                            \
    __syncthreads();

#define GEMM_MAINLOOP()                                                          \
    for (int t = 0; t < ktiles; t++) {                                           \
        int buf = t & 1;                                                         \
        bool pref = (t + 1 < ktiles);                                            \
        float4 f0, f1, f2, f3;                                                   \
        if (pref) {                                                              \
            int nb = buf ^ 1;                                                    \
            const uint32_t* Bp = BtBase + (size_t)(t + 1) * 2048;                \
            cp_async16(sB_u32 + nb * 8192 + tid * 32,      Bp + tid * 8);        \
            cp_async16(sB_u32 + nb * 8192 + tid * 32 + 16, Bp + tid * 8 + 4);    \
            cp_commit();                                                         \
            const float4* Ap4 = (const float4*)(Aptr + (size_t)(t + 1) * 32);    \
            f0 = Ap4[0]; f1 = Ap4[1]; f2 = Ap4[2]; f3 = Ap4[3];                  \
        }                                                                        \
        uint4 fb[4];                                                             \
        _Pragma("unroll") for (int ni = 0; ni < 4; ni++) {                       \
            int n0 = wn + ni * 8 + rr;                                           \
            fb[ni] = *(uint4*)&sB[buf][n0 * 16 + frot];                          \
        }                                                                        \
        _Pragma("unroll") for (int mi = 0; mi < 4; mi++) {                       \
            int r0 = wm + mi * 16 + rr;                                          \
            uint4 lo = *(uint4*)&sA[buf][r0 * 16 + frot];                        \
            uint4 hi = *(uint4*)&sA[buf][(r0 + 8) * 16 + frot];                  \
            _Pragma("unroll") for (int ni = 0; ni < 4; ni++) {                   \
                mma16(acc[mi][ni], lo.x, hi.x, lo.y, hi.y, fb[ni].x, fb[ni].y);  \
                mma16(acc[mi][ni], lo.z, hi.z, lo.w, hi.w, fb[ni].z, fb[ni].w);  \
            }                                                                    \
        }                                                                        \
        if (pref) {                                                              \
            GEMM_A_STORE(buf ^ 1, f0, f1, f2, f3);                               \
            cp_wait0();                                                          \
        }                                                                        \
        __syncthreads();                                                         \
    }

// ---------------- generic GEMM (plain / gelu), row-major output --------------
template<bool GELU>
__global__ void __launch_bounds__(256) gemm_tc(
    const float* __restrict__ A, const uint32_t* __restrict__ Bt,
    const float* __restrict__ bias, const float* __restrict__ res,
    float* __restrict__ C, int M, int N, int K)
{
    __shared__ uint32_t sA[2][2048];
    __shared__ uint32_t sB[2][2048];
    int bm = blockIdx.y * 128, bn = blockIdx.x * 128;
    int ktiles = K / 32;

    GEMM_PROLOGUE();
    const float* Aptr = A + (size_t)(bm + arow) * K + achk * 16;
    const uint32_t* BtBase = Bt + ((size_t)(bn >> 7) * ktiles) * 2048;
    GEMM_LOAD_TILE0();
    GEMM_MAINLOOP();

    #pragma unroll
    for (int mi = 0; mi < 4; mi++) {
        int row = bm + wm + mi * 16 + rr;
        #pragma unroll
        for (int ni = 0; ni < 4; ni++) {
            int col = bn + wn + ni * 8 + 2 * q4;
            float2 bb = *(const float2*)&bias[col];
            float2 r01 = make_float2(acc[mi][ni][0] + bb.x, acc[mi][ni][1] + bb.y);
            float2 r23 = make_float2(acc[mi][ni][2] + bb.x, acc[mi][ni][3] + bb.y);
            if (GELU) {
                r01.x = gelu_f(r01.x); r01.y = gelu_f(r01.y);
                r23.x = gelu_f(r23.x); r23.y = gelu_f(r23.y);
            }
            if (res) {
                float2 v0 = *(const float2*)&res[(size_t)row * N + col];
                float2 v1 = *(const float2*)&res[(size_t)(row + 8) * N + col];
                r01.x += v0.x; r01.y += v0.y;
                r23.x += v1.x; r23.y += v1.y;
            }
            *(float2*)&C[(size_t)row * N + col] = r01;
            *(float2*)&C[(size_t)(row + 8) * N + col] = r23;
        }
    }
}

// ---------------- fused QKV GEMM: epilogue writes fp16 attention images ------
__global__ void __launch_bounds__(256) gemm_qkv(
    const float* __restrict__ A,
    const uint32_t* __restrict__ wq_t, const uint32_t* __restrict__ wk_t,
    const uint32_t* __restrict__ wv_t,
    const float* __restrict__ bq, const float* __restrict__ bk,
    const float* __restrict__ bv,
    const float* __restrict__ cosb, const float* __restrict__ sinb,
    uint32_t* __restrict__ Qo, uint32_t* __restrict__ Ko, uint32_t* __restrict__ Vo)
{
    __shared__ uint32_t sA[2][2048];
    __shared__ uint32_t sB[2][2048];
    const int K = Dc;
    int which = blockIdx.x >> 3;          // 0=Q 1=K 2=V
    int bnl   = (blockIdx.x & 7) * 128;
    int bm    = blockIdx.y * 128;
    int ktiles = K / 32;

    const uint32_t* Bt = (which == 0) ? wq_t : (which == 1) ? wk_t : wv_t;
    const float* bias  = (which == 0) ? bq   : (which == 1) ? bk   : bv;

    GEMM_PROLOGUE();
    const float* Aptr = A + (size_t)(bm + arow) * K + achk * 16;
    const uint32_t* BtBase = Bt + ((size_t)(bnl >> 7) * ktiles) * 2048;
    GEMM_LOAD_TILE0();
    GEMM_MAINLOOP();

    // epilogue: bias, RoPE (Q/K), write fp16 images
    #pragma unroll
    for (int mi = 0; mi < 4; mi++) {
        int row = bm + wm + mi * 16 + rr;         // and row+8
        int bI = row >> 11;
        int t0 = row & (Tc - 1);
        #pragma unroll
        for (int ni = 0; ni < 4; ni++) {
            int col = bnl + wn + ni * 8 + 2 * q4;
            int hh = col >> 6;
            int dh = col & 63;
            int d1 = dh + 1;
            int ii = dh >> 1;
            int bh = bI * 16 + hh;
            float2 bb = *(const float2*)&bias[col];
            float p0 = acc[mi][ni][0] + bb.x, p1 = acc[mi][ni][1] + bb.y;
            float p2 = acc[mi][ni][2] + bb.x, p3 = acc[mi][ni][3] + bb.y;
            if (which < 2) {
                size_t basebh = (size_t)bh * Tc;
                size_t ci0 = (basebh + t0) * NBc + ii;
                size_t ci1 = (basebh + t0 + 8) * NBc + ii;
                float c0 = cosb[ci0], s0 = sinb[ci0];
                float c1 = cosb[ci1], s1 = sinb[ci1];
                float o1 = p0 * c0 - p1 * s0, o2 = p0 * s0 + p1 * c0;
                float o3 = p2 * c1 - p3 * s1, o4 = p2 * s1 + p3 * c1;
                p0 = o1; p1 = o2; p2 = o3; p3 = o4;
            }
            // fragment position for k-pair (dh, dh+1)
            int kk = dh & 31, sl = dh >> 5;
            int g = (kk >> 1) & 3;
            int sub = ((kk >> 3) & 1) + 2 * ((kk >> 4) & 1);
            if (which == 0) {
                int qbi = t0 >> 7, r = t0 & 127;
                uint32_t* dst = Qo + ((size_t)(bh * 16 + qbi)) * 4096;
                int blk = 4 * ((g + r) & 3);      // (r+8)&3 == r&3
                dst[sl * 2048 + r * 16 + blk + sub]       = pack2(p0 * 0.125f, p1 * 0.125f);
                dst[sl * 2048 + (r + 8) * 16 + blk + sub] = pack2(p2 * 0.125f, p3 * 0.125f);
            } else if (which == 1) {
                int kti = t0 >> 6, n = t0 & 63, n8 = n + 8;
                uint32_t* dst = Ko + ((size_t)(bh * 32 + kti)) * 2048;
                dst[sl * 1024 + n * 16  + 4 * ((g + n)  & 3) + sub] = pack2(p0, p1);
                dst[sl * 1024 + n8 * 16 + 4 * ((g + n8) & 3) + sub] = pack2(p2, p3);
            } else {
                int kti = t0 >> 6, tl = t0 & 63, t8 = tl + 8;
                __half* dst = (__half*)(Vo + ((size_t)(bh * 32 + kti)) * 2048);
                // scalar half stores: value at (key, d)
                int kkA = tl & 31, slA = tl >> 5;
                int gA = (kkA >> 1) & 3, subA = ((kkA >> 3) & 1) + 2 * ((kkA >> 4) & 1);
                int kkB = t8 & 31, slB = t8 >> 5;
                int gB = (kkB >> 1) & 3, subB = ((kkB >> 3) & 1) + 2 * ((kkB >> 4) & 1);
                int hA = tl & 1, hB = t8 & 1;
                dst[2 * (slA * 1024 + dh * 16 + 4 * ((gA + dh) & 3) + subA) + hA] = __float2half(p0);
                dst[2 * (slA * 1024 + d1 * 16 + 4 * ((gA + d1) & 3) + subA) + hA] = __float2half(p1);
                dst[2 * (slB * 1024 + dh * 16 + 4 * ((gB + dh) & 3) + subB) + hB] = __float2half(p2);
                dst[2 * (slB * 1024 + d1 * 16 + 4 * ((gB + d1) & 3) + subB) + hB] = __float2half(p3);
            }
        }
    }
}

// ---------------- fp16 flash attention, register-resident P ------------------
__global__ void __launch_bounds__(256, 2) attn_tc(
    const uint32_t* __restrict__ Qimg, const uint32_t* __restrict__ Kimg,
    const uint32_t* __restrict__ Vimg, float* __restrict__ O)
{
    extern __shared__ uint32_t smu[];
    uint32_t* sQ = smu;            // [2 slabs][128][16] = 4096
    uint32_t* sK = smu + 4096;     // 2 buf x [2 slabs][64][16] = 2x2048
    uint32_t* sV = smu + 8192;     // 2 buf x 2048

    uint32_t sQu = (uint32_t)__cvta_generic_to_shared(sQ);
    uint32_t sKu = (uint32_t)__cvta_generic_to_shared(sK);
    uint32_t sVu = (uint32_t)__cvta_generic_to_shared(sV);

    int tid = threadIdx.x, lane = tid & 31, warp = tid >> 5;
    int q4 = lane & 3, rr = lane >> 2;
    int bh = blockIdx.y;
    int b = bh >> 4, h = bh & 15;
    int qb = gridDim.x - 1 - blockIdx.x;

    const uint32_t* Qg = Qimg + ((size_t)(bh * 16 + qb)) * 4096;
    const uint32_t* Kg = Kimg + ((size_t)bh * 32) * 2048;
    const uint32_t* Vg = Vimg + ((size_t)bh * 32) * 2048;

    // group 0: Q tile (16KB) + K/V tile 0 (8KB each)
    #pragma unroll
    for (int j = 0; j < 4; j++) {
        int c = tid + 256 * j;
        cp_async16(sQu + c * 16, Qg + c * 4);
    }
    #pragma unroll
    for (int j = 0; j < 2; j++) {
        int c = tid + 256 * j;
        cp_async16(sKu + c * 16, Kg + c * 4);
        cp_async16(sVu + c * 16, Vg + c * 4);
    }
    cp_commit();

    float m0 = -1e30f, m1 = -1e30f, l0 = 0.f, l1 = 0.f;
    float o[8][4];
    #pragma unroll
    for (int ni = 0; ni < 8; ni++)
        #pragma unroll
        for (int j = 0; j < 4; j++) o[ni][j] = 0.f;

    int r0 = 16 * warp + rr;
    int rowg = qb * 128 + r0;
    int frot = 4 * ((q4 + rr) & 3);

    int nkt = 2 * qb + 2;
    for (int kt = 0; kt < nkt; kt++) {
        int buf = kt & 1;
        bool pref = (kt + 1 < nkt);
        if (pref) {
            int nb = buf ^ 1;
            const uint32_t* Kp = Kg + (size_t)(kt + 1) * 2048;
            const uint32_t* Vp = Vg + (size_t)(kt + 1) * 2048;
            #pragma unroll
            for (int j = 0; j < 2; j++) {
                int c = tid + 256 * j;
                cp_async16(sKu + nb * 8192 + c * 16, Kp + c * 4);
                cp_async16(sVu + nb * 8192 + c * 16, Vp + c * 4);
            }
            cp_commit();
            asm volatile("cp.async.wait_group 1;" ::: "memory");
        } else {
            asm volatile("cp.async.wait_group 0;" ::: "memory");
        }
        __syncthreads();

        const uint32_t* sKb = sK + buf * 2048;
        const uint32_t* sVb = sV + buf * 2048;

        // S = Q K^T : warp 16x64, k=dh in 2 slabs of 32
        float s[8][4];
        #pragma unroll
        for (int ni = 0; ni < 8; ni++)
            #pragma unroll
            for (int j = 0; j < 4; j++) s[ni][j] = 0.f;

        #pragma unroll
        for (int sl = 0; sl < 2; sl++) {
            uint4 lo = *(uint4*)&sQ[sl * 2048 + r0 * 16 + frot];
            uint4 hi = *(uint4*)&sQ[sl * 2048 + (r0 + 8) * 16 + frot];
            #pragma unroll
            for (int ni = 0; ni < 8; ni++) {
                int n0 = ni * 8 + rr;
                uint4 fb = *(uint4*)&sKb[sl * 1024 + n0 * 16 + frot];
                mma16(s[ni], lo.x, hi.x, lo.y, hi.y, fb.x, fb.y);
                mma16(s[ni], lo.z, hi.z, lo.w, hi.w, fb.z, fb.w);
            }
        }

        // causal mask (diagonal tiles only)
        if (kt >= 2 * qb) {
            #pragma unroll
            for (int ni = 0; ni < 8; ni++) {
                int colg = kt * 64 + ni * 8 + 2 * q4;
                if (colg     > rowg)     s[ni][0] = -1e30f;
                if (colg + 1 > rowg)     s[ni][1] = -1e30f;
                if (colg     > rowg + 8) s[ni][2] = -1e30f;
                if (colg + 1 > rowg + 8) s[ni][3] = -1e30f;
            }
        }

        // online softmax (rows r0, r0+8), P left in s[][]
        float mx0 = -1e30f, mx1 = -1e30f;
        #pragma unroll
        for (int ni = 0; ni < 8; ni++) {
            mx0 = fmaxf(mx0, fmaxf(s[ni][0], s[ni][1]));
            mx1 = fmaxf(mx1, fmaxf(s[ni][2], s[ni][3]));
        }
        mx0 = fmaxf(mx0, __shfl_xor_sync(0xffffffffu, mx0, 1));
        mx0 = fmaxf(mx0, __shfl_xor_sync(0xffffffffu, mx0, 2));
        mx1 = fmaxf(mx1, __shfl_xor_sync(0xffffffffu, mx1, 1));
        mx1 = fmaxf(mx1, __shfl_xor_sync(0xffffffffu, mx1, 2));
        float mn0 = fmaxf(m0, mx0), mn1 = fmaxf(m1, mx1);
        float al0 = __expf(m0 - mn0), al1 = __expf(m1 - mn1);
        m0 = mn0; m1 = mn1;

        float sum0 = 0.f, sum1 = 0.f;
        #pragma unroll
        for (int ni = 0; ni < 8; ni++) {
            s[ni][0] = __expf(s[ni][0] - m0);
            s[ni][1] = __expf(s[ni][1] - m0);
            s[ni][2] = __expf(s[ni][2] - m1);
            s[ni][3] = __expf(s[ni][3] - m1);
            sum0 += s[ni][0] + s[ni][1];
            sum1 += s[ni][2] + s[ni][3];
        }
        sum0 += __shfl_xor_sync(0xffffffffu, sum0, 1);
        sum0 += __shfl_xor_sync(0xffffffffu, sum0, 2);
        sum1 += __shfl_xor_sync(0xffffffffu, sum1, 1);
        sum1 += __shfl_xor_sync(0xffffffffu, sum1, 2);
        l0 = l0 * al0 + sum0;
        l1 = l1 * al1 + sum1;

        #pragma unroll
        for (int ni = 0; ni < 8; ni++) {
            o[ni][0] *= al0; o[ni][1] *= al0;
            o[ni][2] *= al1; o[ni][3] *= al1;
        }

        // O += P V : P is register-resident (S C-fragment == PV A-fragment)
        #pragma unroll
        for (int sl = 0; sl < 2; sl++) {
            int bs = sl * 4;
            uint32_t a00 = pack2(s[bs+0][0], s[bs+0][1]);
            uint32_t a01 = pack2(s[bs+0][2], s[bs+0][3]);
            uint32_t a10 = pack2(s[bs+1][0], s[bs+1][1]);
            uint32_t a11 = pack2(s[bs+1][2], s[bs+1][3]);
            uint32_t a20 = pack2(s[bs+2][0], s[bs+2][1]);
            uint32_t a21 = pack2(s[bs+2][2], s[bs+2][3]);
            uint32_t a30 = pack2(s[bs+3][0], s[bs+3][1]);
            uint32_t a31 = pack2(s[bs+3][2], s[bs+3][3]);
            #pragma unroll
            for (int nj = 0; nj < 8; nj++) {
                int n0 = nj * 8 + rr;
                uint4 fb = *(uint4*)&sVb[sl * 1024 + n0 * 16 + frot];
                mma16(o[nj], a00, a01, a10, a11, fb.x, fb.y);
                mma16(o[nj], a20, a21, a30, a31, fb.z, fb.w);
            }
        }
        __syncthreads();
    }

    // epilogue: /l, write row-major [B,T,H,DH]
    float inv0 = 1.f / l0, inv1 = 1.f / l1;
    int t0 = qb * 128 + r0;
    #pragma unroll
    for (int ni = 0; ni < 8; ni++) {
        int dh = ni * 8 + 2 * q4;
        *(float2*)&O[((((size_t)b * Tc + t0) * Hc + h) * DHc) + dh] =
            make_float2(o[ni][0] * inv0, o[ni][1] * inv0);
        *(float2*)&O[((((size_t)b * Tc + t0 + 8) * Hc + h) * DHc) + dh] =
            make_float2(o[ni][2] * inv1, o[ni][3] * inv1);
    }
}

// ---------------- launch ----------------
extern "C" void kernel_launch(void* const* d_in, const int* in_sizes, int n_in,
                              void* d_out, int out_size)
{
    const float* x    = (const float*)d_in[0];
    const float* cosb = (const float*)d_in[1];
    const float* sinb = (const float*)d_in[2];
    const float* Wq  = (const float*)d_in[4];
    const float* bq  = (const float*)d_in[5];
    const float* Wk  = (const float*)d_in[6];
    const float* bk  = (const float*)d_in[7];
    const float* Wv  = (const float*)d_in[8];
    const float* bv  = (const float*)d_in[9];
    const float* Wo  = (const float*)d_in[10];
    const float* bo  = (const float*)d_in[11];
    const float* g1  = (const float*)d_in[12];
    const float* b1n = (const float*)d_in[13];
    const float* g2  = (const float*)d_in[14];
    const float* b2n = (const float*)d_in[15];
    const float* W1  = (const float*)d_in[16];
    const float* bf1 = (const float*)d_in[17];
    const float* W2  = (const float*)d_in[18];
    const float* bf2 = (const float*)d_in[19];
    float* out = (float*)d_out;

    float *h, *attn, *x2, *ffn;
    uint32_t *q, *k, *v;
    uint32_t *wq_t, *wk_t, *wv_t, *wo_t, *w1_t, *w2_t;
    cudaGetSymbolAddress((void**)&h,    g_h);
    cudaGetSymbolAddress((void**)&q,    g_q);
    cudaGetSymbolAddress((void**)&k,    g_k);
    cudaGetSymbolAddress((void**)&v,    g_v);
    cudaGetSymbolAddress((void**)&attn, g_attn);
    cudaGetSymbolAddress((void**)&x2,   g_x2);
    cudaGetSymbolAddress((void**)&ffn,  g_ffn);
    cudaGetSymbolAddress((void**)&wq_t, g_wq_t);
    cudaGetSymbolAddress((void**)&wk_t, g_wk_t);
    cudaGetSymbolAddress((void**)&wv_t, g_wv_t);
    cudaGetSymbolAddress((void**)&wo_t, g_wo_t);
    cudaGetSymbolAddress((void**)&w1_t, g_w1_t);
    cudaGetSymbolAddress((void**)&w2_t, g_w2_t);

    int attnSmem = 12288 * (int)sizeof(uint32_t);   // 49152 B
    cudaFuncSetAttribute(attn_tc, cudaFuncAttributeMaxDynamicSharedMemorySize, attnSmem);

    // fp16 weight prep: one launch
    prep_all<<<3072, 256>>>(Wq, Wk, Wv, Wo, W1, W2,
                            wq_t, wk_t, wv_t, wo_t, w1_t, w2_t);

    dim3 blk(256);
    dim3 gProj(Dc / 128, ROWS / 128);        // (8, 32)
    dim3 gQkv(3 * Dc / 128, ROWS / 128);     // (24, 32)
    dim3 gFfn1(4 * Dc / 128, ROWS / 128);    // (32, 32)

    // 1. h = LN(x)
    ln_kernel<<<ROWS, blk>>>(x, g1, b1n, h);
    // 2. fused QKV projection + RoPE -> fp16 attention images
    gemm_qkv<<<gQkv, blk>>>(h, wq_t, wk_t, wv_t, bq, bk, bv, cosb, sinb, q, k, v);
    // 3. causal flash attention (fp16 images in, row-major fp32 out)
    dim3 gAttn(Tc / 128, Bc * Hc);
    attn_tc<<<gAttn, blk, attnSmem>>>(q, k, v, attn);
    // 4. x2 = x + attn @ Wo + bo
    gemm_tc<false><<<gProj, blk>>>(attn, wo_t, bo, x, x2, ROWS, Dc, Dc);
    // 5. h = LN(x2)
    ln_kernel<<<ROWS, blk>>>(x2, g2, b2n, h);
    // 6. ffn = gelu(h @ W1 + bf1)
    gemm_tc<true><<<gFfn1, blk>>>(h, w1_t, bf1, nullptr, ffn, ROWS, 4 * Dc, Dc);
    // 7. out = x2 + ffn @ W2 + bf2
    gemm_tc<false><<<gProj, blk>>>(ffn, w2_t, bf2, x2, out, ROWS, Dc, 4 * Dc);
}

// round 17
// speedup vs baseline: 1.6321x; 1.6321x over previous
#include <cuda_runtime.h>
#include <cuda_fp16.h>
#include <math.h>
#include <stdint.h>

// Problem constants
#define Bc 2
#define Tc 2048
#define Dc 1024
#define Hc 16
#define DHc 64
#define NBc 32
#define ROWS (Bc*Tc)          // 4096

// ---------------- scratch ----------------
__device__ float    g_h   [ (size_t)ROWS * Dc ];       // row-major (LN out)
__device__ uint32_t g_q   [ (size_t)ROWS * Dc / 2 ];   // Q fp16 A-image
__device__ uint32_t g_k   [ (size_t)ROWS * Dc / 2 ];   // K fp16 B-image
__device__ uint32_t g_v   [ (size_t)ROWS * Dc / 2 ];   // V fp16 B-image (n=dh, k=key)
__device__ float    g_attn[ (size_t)ROWS * Dc ];       // row-major [B,T,H,DH]
__device__ float    g_x2  [ (size_t)ROWS * Dc ];
__device__ float    g_ffn [ (size_t)ROWS * 4 * Dc ];
// pre-swizzled fp16 weight tiles: [n_tile][k_slab32][2048 half2-units]
__device__ uint32_t g_wq_t[ (size_t)Dc * Dc / 2 ];
__device__ uint32_t g_wk_t[ (size_t)Dc * Dc / 2 ];
__device__ uint32_t g_wv_t[ (size_t)Dc * Dc / 2 ];
__device__ uint32_t g_wo_t[ (size_t)Dc * Dc / 2 ];
__device__ uint32_t g_w1_t[ (size_t)Dc * 4 * Dc / 2 ];
__device__ uint32_t g_w2_t[ (size_t)Dc * 4 * Dc / 2 ];

// ---------------- helpers ----------------
__device__ __forceinline__ uint32_t pack2(float a, float b)
{
    __half2 h = __floats2half2_rn(a, b);
    return *(uint32_t*)&h;
}

__device__ __forceinline__ void mma16(float c[4],
    uint32_t a0, uint32_t a1, uint32_t a2, uint32_t a3,
    uint32_t b0, uint32_t b1)
{
    asm volatile(
        "mma.sync.aligned.m16n8k16.row.col.f32.f16.f16.f32 "
        "{%0,%1,%2,%3}, {%4,%5,%6,%7}, {%8,%9}, {%0,%1,%2,%3};"
        : "+f"(c[0]), "+f"(c[1]), "+f"(c[2]), "+f"(c[3])
        : "r"(a0), "r"(a1), "r"(a2), "r"(a3), "r"(b0), "r"(b1));
}

__device__ __forceinline__ void cp_async16(uint32_t smem_dst, const void* gptr)
{
    asm volatile("cp.async.cg.shared.global [%0], [%1], 16;"
                 :: "r"(smem_dst), "l"(gptr));
}
__device__ __forceinline__ void cp_commit()  { asm volatile("cp.async.commit_group;"); }
__device__ __forceinline__ void cp_wait0()   { asm volatile("cp.async.wait_group 0;" ::: "memory"); }

__device__ __forceinline__ float gelu_f(float v)
{
    return 0.5f * v * (1.0f + erff(v * 0.70710678118654752f));
}

// ---------------- weight prep: W[K][N] -> fp16 interleaved B tiles ------------
__global__ void __launch_bounds__(256) prep_all(
    const float* __restrict__ Wq, const float* __restrict__ Wk,
    const float* __restrict__ Wv, const float* __restrict__ Wo,
    const float* __restrict__ W1, const float* __restrict__ W2,
    uint32_t* __restrict__ wq_t, uint32_t* __restrict__ wk_t,
    uint32_t* __restrict__ wv_t, uint32_t* __restrict__ wo_t,
    uint32_t* __restrict__ w1_t, uint32_t* __restrict__ w2_t)
{
    int id = blockIdx.x, tid = threadIdx.x;
    const float* W; uint32_t* out; int N, kslabs, ks, nt;
    if (id < 1024) {
        int m = id >> 8, local = id & 255;
        const float* Ws[4] = {Wq, Wk, Wv, Wo};
        uint32_t* Os[4] = {wq_t, wk_t, wv_t, wo_t};
        W = Ws[m]; out = Os[m]; N = Dc; kslabs = 32;
        ks = local & 31; nt = local >> 5;
    } else if (id < 2048) {
        int local = id - 1024;
        W = W1; out = w1_t; N = 4 * Dc; kslabs = 32;
        ks = local & 31; nt = local >> 5;
    } else {
        int local = id - 2048;
        W = W2; out = w2_t; N = Dc; kslabs = 128;
        ks = local & 127; nt = local >> 7;
    }
    uint32_t* dst = out + ((size_t)nt * kslabs + ks) * 2048;
    const float* Wb = W + (size_t)(ks * 32) * N + nt * 128;
    #pragma unroll
    for (int j = 0; j < 2; j++) {
        int u = tid + 256 * j;
        int n = u & 127, g = u >> 7;
        const float* p = Wb + n;
        float v0 = p[(size_t)(2*g)      * N], v1 = p[(size_t)(2*g + 1)  * N];
        float v2 = p[(size_t)(2*g + 8)  * N], v3 = p[(size_t)(2*g + 9)  * N];
        float v4 = p[(size_t)(2*g + 16) * N], v5 = p[(size_t)(2*g + 17) * N];
        float v6 = p[(size_t)(2*g + 24) * N], v7 = p[(size_t)(2*g + 25) * N];
        uint4 o = make_uint4(pack2(v0, v1), pack2(v2, v3),
                             pack2(v4, v5), pack2(v6, v7));
        *(uint4*)&dst[n * 16 + 4 * ((g + n) & 3)] = o;
    }
}

// ---------------- LayerNorm (row-major out) -----------------------------------
__global__ void __launch_bounds__(256) ln_kernel(const float* __restrict__ x,
                                                 const float* __restrict__ g,
                                                 const float* __restrict__ b,
                                                 float* __restrict__ o)
{
    __shared__ float sred[16];
    int row = blockIdx.x;
    int tid = threadIdx.x;
    const float* xr = x + (size_t)row * Dc;
    float4 v = *(const float4*)&xr[tid * 4];
    float s  = v.x + v.y + v.z + v.w;
    float s2 = v.x*v.x + v.y*v.y + v.z*v.z + v.w*v.w;
    #pragma unroll
    for (int off = 16; off; off >>= 1) {
        s  += __shfl_xor_sync(0xffffffffu, s,  off);
        s2 += __shfl_xor_sync(0xffffffffu, s2, off);
    }
    if ((tid & 31) == 0) { sred[tid >> 5] = s; sred[8 + (tid >> 5)] = s2; }
    __syncthreads();
    float S = 0.f, S2 = 0.f;
    #pragma unroll
    for (int i = 0; i < 8; i++) { S += sred[i]; S2 += sred[8 + i]; }
    float mean = S * (1.0f / Dc);
    float var  = S2 * (1.0f / Dc) - mean * mean;
    float rstd = rsqrtf(var + 1e-5f);
    float4 gv = *(const float4*)&g[tid * 4];
    float4 bv = *(const float4*)&b[tid * 4];
    float4 ov;
    ov.x = (v.x - mean) * rstd * gv.x + bv.x;
    ov.y = (v.y - mean) * rstd * gv.y + bv.y;
    ov.z = (v.z - mean) * rstd * gv.z + bv.z;
    ov.w = (v.w - mean) * rstd * gv.w + bv.w;
    *(float4*)&o[(size_t)row * Dc + tid * 4] = ov;
}

// =====================  fp16 GEMM building blocks (r15-proven) ================
#define GEMM_PROLOGUE()                                                          \
    int tid  = threadIdx.x;                                                      \
    int lane = tid & 31;                                                         \
    int warp = tid >> 5;                                                         \
    int q4 = lane & 3, rr = lane >> 2;                                           \
    int wm = (warp & 1) * 64;                                                    \
    int wn = (warp >> 1) * 32;                                                   \
    int arow = tid >> 1;                                                         \
    int achk = tid & 1;                                                          \
    int ab = arow * 16 + 2 * achk;                                               \
    int ax = arow & 3;                                                           \
    uint32_t sB_u32 = (uint32_t)__cvta_generic_to_shared(&sB[0][0]);             \
    float acc[4][4][4];                                                          \
    _Pragma("unroll") for (int i = 0; i < 4; i++)                                \
        _Pragma("unroll") for (int j = 0; j < 4; j++)                            \
            _Pragma("unroll") for (int r = 0; r < 4; r++) acc[i][j][r] = 0.f;    \
    int frot = 4 * ((q4 + rr) & 3);

#define GEMM_A_STORE(dstbuf, f0, f1, f2, f3)                                     \
    {                                                                            \
        uint32_t u0 = pack2(f0.x, f0.y), u1 = pack2(f0.z, f0.w);                 \
        uint32_t u2 = pack2(f1.x, f1.y), u3 = pack2(f1.z, f1.w);                 \
        uint32_t u4 = pack2(f2.x, f2.y), u5 = pack2(f2.z, f2.w);                 \
        uint32_t u6 = pack2(f3.x, f3.y), u7 = pack2(f3.z, f3.w);                 \
        *(uint2*)&sA[dstbuf][ab + 4 * ((0 + ax) & 3)] = make_uint2(u0, u4);      \
        *(uint2*)&sA[dstbuf][ab + 4 * ((1 + ax) & 3)] = make_uint2(u1, u5);      \
        *(uint2*)&sA[dstbuf][ab + 4 * ((2 + ax) & 3)] = make_uint2(u2, u6);      \
        *(uint2*)&sA[dstbuf][ab + 4 * ((3 + ax) & 3)] = make_uint2(u3, u7);      \
    }

#define GEMM_LOAD_TILE0()                                                        \
    {                                                                            \
        cp_async16(sB_u32 + tid * 32,      BtBase + tid * 8);                    \
        cp_async16(sB_u32 + tid * 32 + 16, BtBase + tid * 8 + 4);                \
        cp_commit();                                                             \
        const float4* Ap4 = (const float4*)Aptr;                                 \
        float4 f0 = Ap4[0], f1 = Ap4[1], f2 = Ap4[2], f3 = Ap4[3];               \
        GEMM_A_STORE(0, f0, f1, f2, f3);                                         \
        cp_wait0();                                                              \
    }                                                                            \
    __syncthreads();

#define GEMM_MAINLOOP()                                                          \
    for (int t = 0; t < ktiles; t++) {                                           \
        int buf = t & 1;                                                         \
        bool pref = (t + 1 < ktiles);                                            \
        float4 f0, f1, f2, f3;                                                   \
        if (pref) {                                                              \
            int nb = buf ^ 1;                                                    \
            const uint32_t* Bp = BtBase + (size_t)(t + 1) * 2048;                \
            cp_async16(sB_u32 + nb * 8192 + tid * 32,      Bp + tid * 8);        \
            cp_async16(sB_u32 + nb * 8192 + tid * 32 + 16, Bp + tid * 8 + 4);    \
            cp_commit();                                                         \
            const float4* Ap4 = (const float4*)(Aptr + (size_t)(t + 1) * 32);    \
            f0 = Ap4[0]; f1 = Ap4[1]; f2 = Ap4[2]; f3 = Ap4[3];                  \
        }                                                                        \
        uint4 fb[4];                                                             \
        _Pragma("unroll") for (int ni = 0; ni < 4; ni++) {                       \
            int n0 = wn + ni * 8 + rr;                                           \
            fb[ni] = *(uint4*)&sB[buf][n0 * 16 + frot];                          \
        }                                                                        \
        _Pragma("unroll") for (int mi = 0; mi < 4; mi++) {                       \
            int r0 = wm + mi * 16 + rr;                                          \
            uint4 lo = *(uint4*)&sA[buf][r0 * 16 + frot];                        \
            uint4 hi = *(uint4*)&sA[buf][(r0 + 8) * 16 + frot];                  \
            _Pragma("unroll") for (int ni = 0; ni < 4; ni++) {                   \
                mma16(acc[mi][ni], lo.x, hi.x, lo.y, hi.y, fb[ni].x, fb[ni].y);  \
                mma16(acc[mi][ni], lo.z, hi.z, lo.w, hi.w, fb[ni].z, fb[ni].w);  \
            }                                                                    \
        }                                                                        \
        if (pref) {                                                              \
            GEMM_A_STORE(buf ^ 1, f0, f1, f2, f3);                               \
            cp_wait0();                                                          \
        }                                                                        \
        __syncthreads();                                                         \
    }

// ---------------- generic GEMM (plain / gelu), row-major output --------------
template<bool GELU>
__global__ void __launch_bounds__(256) gemm_tc(
    const float* __restrict__ A, const uint32_t* __restrict__ Bt,
    const float* __restrict__ bias, const float* __restrict__ res,
    float* __restrict__ C, int M, int N, int K)
{
    __shared__ uint32_t sA[2][2048];
    __shared__ uint32_t sB[2][2048];
    int bm = blockIdx.y * 128, bn = blockIdx.x * 128;
    int ktiles = K / 32;

    GEMM_PROLOGUE();
    const float* Aptr = A + (size_t)(bm + arow) * K + achk * 16;
    const uint32_t* BtBase = Bt + ((size_t)(bn >> 7) * ktiles) * 2048;
    GEMM_LOAD_TILE0();
    GEMM_MAINLOOP();

    #pragma unroll
    for (int mi = 0; mi < 4; mi++) {
        int row = bm + wm + mi * 16 + rr;
        #pragma unroll
        for (int ni = 0; ni < 4; ni++) {
            int col = bn + wn + ni * 8 + 2 * q4;
            float2 bb = *(const float2*)&bias[col];
            float2 r01 = make_float2(acc[mi][ni][0] + bb.x, acc[mi][ni][1] + bb.y);
            float2 r23 = make_float2(acc[mi][ni][2] + bb.x, acc[mi][ni][3] + bb.y);
            if (GELU) {
                r01.x = gelu_f(r01.x); r01.y = gelu_f(r01.y);
                r23.x = gelu_f(r23.x); r23.y = gelu_f(r23.y);
            }
            if (res) {
                float2 v0 = *(const float2*)&res[(size_t)row * N + col];
                float2 v1 = *(const float2*)&res[(size_t)(row + 8) * N + col];
                r01.x += v0.x; r01.y += v0.y;
                r23.x += v1.x; r23.y += v1.y;
            }
            *(float2*)&C[(size_t)row * N + col] = r01;
            *(float2*)&C[(size_t)(row + 8) * N + col] = r23;
        }
    }
}

// ---------------- fused QKV GEMM: fp16 image epilogue (V staged via SMEM) ----
__global__ void __launch_bounds__(256) gemm_qkv(
    const float* __restrict__ A,
    const uint32_t* __restrict__ wq_t, const uint32_t* __restrict__ wk_t,
    const uint32_t* __restrict__ wv_t,
    const float* __restrict__ bq, const float* __restrict__ bk,
    const float* __restrict__ bv,
    const float* __restrict__ cosb, const float* __restrict__ sinb,
    uint32_t* __restrict__ Qo, uint32_t* __restrict__ Ko, uint32_t* __restrict__ Vo)
{
    __shared__ uint32_t sAll[8192];     // 32 KB: mainloop buffers, then V staging
    uint32_t (*sA)[2048] = (uint32_t(*)[2048])sAll;
    uint32_t (*sB)[2048] = (uint32_t(*)[2048])(sAll + 4096);
    const int K = Dc;
    int which = blockIdx.x >> 3;          // 0=Q 1=K 2=V
    int bnl   = (blockIdx.x & 7) * 128;
    int bm    = blockIdx.y * 128;
    int ktiles = K / 32;

    const uint32_t* Bt = (which == 0) ? wq_t : (which == 1) ? wk_t : wv_t;
    const float* bias  = (which == 0) ? bq   : (which == 1) ? bk   : bv;

    GEMM_PROLOGUE();
    const float* Aptr = A + (size_t)(bm + arow) * K + achk * 16;
    const uint32_t* BtBase = Bt + ((size_t)(bnl >> 7) * ktiles) * 2048;
    GEMM_LOAD_TILE0();
    GEMM_MAINLOOP();

    int bI = (bm + wm) >> 11;             // batch (uniform per CTA row-block)
    #pragma unroll
    for (int mi = 0; mi < 4; mi++) {
        int row = bm + wm + mi * 16 + rr;         // and row+8
        int t0 = row & (Tc - 1);
        #pragma unroll
        for (int ni = 0; ni < 4; ni++) {
            int col = bnl + wn + ni * 8 + 2 * q4;
            int hh = col >> 6;
            int dh = col & 63;
            int d1 = dh + 1;
            int ii = dh >> 1;
            int bh = bI * 16 + hh;
            float2 bb = *(const float2*)&bias[col];
            float p0 = acc[mi][ni][0] + bb.x, p1 = acc[mi][ni][1] + bb.y;
            float p2 = acc[mi][ni][2] + bb.x, p3 = acc[mi][ni][3] + bb.y;
            if (which < 2) {
                size_t basebh = (size_t)bh * Tc;
                size_t ci0 = (basebh + t0) * NBc + ii;
                size_t ci1 = (basebh + t0 + 8) * NBc + ii;
                float c0 = cosb[ci0], s0 = sinb[ci0];
                float c1 = cosb[ci1], s1 = sinb[ci1];
                float o1 = p0 * c0 - p1 * s0, o2 = p0 * s0 + p1 * c0;
                float o3 = p2 * c1 - p3 * s1, o4 = p2 * s1 + p3 * c1;
                p0 = o1; p1 = o2; p2 = o3; p3 = o4;
            }
            int kk = dh & 31, sl = dh >> 5;
            int g = (kk >> 1) & 3;
            int sub = ((kk >> 3) & 1) + 2 * ((kk >> 4) & 1);
            if (which == 0) {
                int qbi = t0 >> 7, r = t0 & 127;
                uint32_t* dst = Qo + ((size_t)(bh * 16 + qbi)) * 4096;
                int blk = 4 * ((g + r) & 3);
                dst[sl * 2048 + r * 16 + blk + sub]       = pack2(p0 * 0.125f, p1 * 0.125f);
                dst[sl * 2048 + (r + 8) * 16 + blk + sub] = pack2(p2 * 0.125f, p3 * 0.125f);
            } else if (which == 1) {
                int kti = t0 >> 6, n = t0 & 63, n8 = n + 8;
                uint32_t* dst = Ko + ((size_t)(bh * 32 + kti)) * 2048;
                dst[sl * 1024 + n * 16  + 4 * ((g + n)  & 3) + sub] = pack2(p0, p1);
                dst[sl * 1024 + n8 * 16 + 4 * ((g + n8) & 3) + sub] = pack2(p2, p3);
            } else {
                // V: stage scattered half stores into SMEM region (fast), copy later
                int rowLoc = wm + mi * 16 + rr;              // 0..127, +8 stays in block
                int reg = (wm >> 6) * 2 + ((wn + ni * 8 + 2 * q4) >> 6);
                __half* hdst = (__half*)(sAll + reg * 2048);
                int tl = rowLoc & 63, t8 = tl + 8;
                int kkA = tl & 31, slA = tl >> 5;
                int gA = (kkA >> 1) & 3, subA = ((kkA >> 3) & 1) + 2 * ((kkA >> 4) & 1);
                int kkB = t8 & 31, slB = t8 >> 5;
                int gB = (kkB >> 1) & 3, subB = ((kkB >> 3) & 1) + 2 * ((kkB >> 4) & 1);
                int hA = tl & 1, hB = t8 & 1;
                hdst[2 * (slA * 1024 + dh * 16 + 4 * ((gA + dh) & 3) + subA) + hA] = __float2half(p0);
                hdst[2 * (slA * 1024 + d1 * 16 + 4 * ((gA + d1) & 3) + subA) + hA] = __float2half(p1);
                hdst[2 * (slB * 1024 + dh * 16 + 4 * ((gB + dh) & 3) + subB) + hB] = __float2half(p2);
                hdst[2 * (slB * 1024 + d1 * 16 + 4 * ((gB + d1) & 3) + subB) + hB] = __float2half(p3);
            }
        }
    }

    if (which == 2) {
        __syncthreads();
        // copy 4 regions (kti_local, hh_local), each 2048 u32, fully coalesced
        #pragma unroll
        for (int reg = 0; reg < 4; reg++) {
            int kti = ((bm & (Tc - 1)) >> 6) + (reg >> 1);
            int bh  = bI * 16 + (bnl >> 6) + (reg & 1);
            uint32_t* dst = Vo + ((size_t)(bh * 32 + kti)) * 2048;
            const uint32_t* src = sAll + reg * 2048;
            *(uint4*)&dst[tid * 8]     = *(const uint4*)&src[tid * 8];
            *(uint4*)&dst[tid * 8 + 4] = *(const uint4*)&src[tid * 8 + 4];
        }
    }
}

// ---------------- fp16 flash attention, register-resident P (r16-proven) -----
__global__ void __launch_bounds__(256, 2) attn_tc(
    const uint32_t* __restrict__ Qimg, const uint32_t* __restrict__ Kimg,
    const uint32_t* __restrict__ Vimg, float* __restrict__ O)
{
    extern __shared__ uint32_t smu[];
    uint32_t* sQ = smu;            // [2 slabs][128][16] = 4096
    uint32_t* sK = smu + 4096;     // 2 buf x 2048
    uint32_t* sV = smu + 8192;     // 2 buf x 2048

    uint32_t sQu = (uint32_t)__cvta_generic_to_shared(sQ);
    uint32_t sKu = (uint32_t)__cvta_generic_to_shared(sK);
    uint32_t sVu = (uint32_t)__cvta_generic_to_shared(sV);

    int tid = threadIdx.x, lane = tid & 31, warp = tid >> 5;
    int q4 = lane & 3, rr = lane >> 2;
    int bh = blockIdx.y;
    int b = bh >> 4, h = bh & 15;
    int qb = gridDim.x - 1 - blockIdx.x;

    const uint32_t* Qg = Qimg + ((size_t)(bh * 16 + qb)) * 4096;
    const uint32_t* Kg = Kimg + ((size_t)bh * 32) * 2048;
    const uint32_t* Vg = Vimg + ((size_t)bh * 32) * 2048;

    #pragma unroll
    for (int j = 0; j < 4; j++) {
        int c = tid + 256 * j;
        cp_async16(sQu + c * 16, Qg + c * 4);
    }
    #pragma unroll
    for (int j = 0; j < 2; j++) {
        int c = tid + 256 * j;
        cp_async16(sKu + c * 16, Kg + c * 4);
        cp_async16(sVu + c * 16, Vg + c * 4);
    }
    cp_commit();

    float m0 = -1e30f, m1 = -1e30f, l0 = 0.f, l1 = 0.f;
    float o[8][4];
    #pragma unroll
    for (int ni = 0; ni < 8; ni++)
        #pragma unroll
        for (int j = 0; j < 4; j++) o[ni][j] = 0.f;

    int r0 = 16 * warp + rr;
    int rowg = qb * 128 + r0;
    int frot = 4 * ((q4 + rr) & 3);

    int nkt = 2 * qb + 2;
    for (int kt = 0; kt < nkt; kt++) {
        int buf = kt & 1;
        bool pref = (kt + 1 < nkt);
        if (pref) {
            int nb = buf ^ 1;
            const uint32_t* Kp = Kg + (size_t)(kt + 1) * 2048;
            const uint32_t* Vp = Vg + (size_t)(kt + 1) * 2048;
            #pragma unroll
            for (int j = 0; j < 2; j++) {
                int c = tid + 256 * j;
                cp_async16(sKu + nb * 8192 + c * 16, Kp + c * 4);
                cp_async16(sVu + nb * 8192 + c * 16, Vp + c * 4);
            }
            cp_commit();
            asm volatile("cp.async.wait_group 1;" ::: "memory");
        } else {
            asm volatile("cp.async.wait_group 0;" ::: "memory");
        }
        __syncthreads();

        const uint32_t* sKb = sK + buf * 2048;
        const uint32_t* sVb = sV + buf * 2048;

        float s[8][4];
        #pragma unroll
        for (int ni = 0; ni < 8; ni++)
            #pragma unroll
            for (int j = 0; j < 4; j++) s[ni][j] = 0.f;

        #pragma unroll
        for (int sl = 0; sl < 2; sl++) {
            uint4 lo = *(uint4*)&sQ[sl * 2048 + r0 * 16 + frot];
            uint4 hi = *(uint4*)&sQ[sl * 2048 + (r0 + 8) * 16 + frot];
            #pragma unroll
            for (int ni = 0; ni < 8; ni++) {
                int n0 = ni * 8 + rr;
                uint4 fb = *(uint4*)&sKb[sl * 1024 + n0 * 16 + frot];
                mma16(s[ni], lo.x, hi.x, lo.y, hi.y, fb.x, fb.y);
                mma16(s[ni], lo.z, hi.z, lo.w, hi.w, fb.z, fb.w);
            }
        }

        if (kt >= 2 * qb) {
            #pragma unroll
            for (int ni = 0; ni < 8; ni++) {
                int colg = kt * 64 + ni * 8 + 2 * q4;
                if (colg     > rowg)     s[ni][0] = -1e30f;
                if (colg + 1 > rowg)     s[ni][1] = -1e30f;
                if (colg     > rowg + 8) s[ni][2] = -1e30f;
                if (colg + 1 > rowg + 8) s[ni][3] = -1e30f;
            }
        }

        float mx0 = -1e30f, mx1 = -1e30f;
        #pragma unroll
        for (int ni = 0; ni < 8; ni++) {
            mx0 = fmaxf(mx0, fmaxf(s[ni][0], s[ni][1]));
            mx1 = fmaxf(mx1, fmaxf(s[ni][2], s[ni][3]));
        }
        mx0 = fmaxf(mx0, __shfl_xor_sync(0xffffffffu, mx0, 1));
        mx0 = fmaxf(mx0, __shfl_xor_sync(0xffffffffu, mx0, 2));
        mx1 = fmaxf(mx1, __shfl_xor_sync(0xffffffffu, mx1, 1));
        mx1 = fmaxf(mx1, __shfl_xor_sync(0xffffffffu, mx1, 2));
        float mn0 = fmaxf(m0, mx0), mn1 = fmaxf(m1, mx1);
        float al0 = __expf(m0 - mn0), al1 = __expf(m1 - mn1);
        m0 = mn0; m1 = mn1;

        float sum0 = 0.f, sum1 = 0.f;
        #pragma unroll
        for (int ni = 0; ni < 8; ni++) {
            s[ni][0] = __expf(s[ni][0] - m0);
            s[ni][1] = __expf(s[ni][1] - m0);
            s[ni][2] = __expf(s[ni][2] - m1);
            s[ni][3] = __expf(s[ni][3] - m1);
            sum0 += s[ni][0] + s[ni][1];
            sum1 += s[ni][2] + s[ni][3];
        }
        sum0 += __shfl_xor_sync(0xffffffffu, sum0, 1);
        sum0 += __shfl_xor_sync(0xffffffffu, sum0, 2);
        sum1 += __shfl_xor_sync(0xffffffffu, sum1, 1);
        sum1 += __shfl_xor_sync(0xffffffffu, sum1, 2);
        l0 = l0 * al0 + sum0;
        l1 = l1 * al1 + sum1;

        #pragma unroll
        for (int ni = 0; ni < 8; ni++) {
            o[ni][0] *= al0; o[ni][1] *= al0;
            o[ni][2] *= al1; o[ni][3] *= al1;
        }

        #pragma unroll
        for (int sl = 0; sl < 2; sl++) {
            int bs = sl * 4;
            uint32_t a00 = pack2(s[bs+0][0], s[bs+0][1]);
            uint32_t a01 = pack2(s[bs+0][2], s[bs+0][3]);
            uint32_t a10 = pack2(s[bs+1][0], s[bs+1][1]);
            uint32_t a11 = pack2(s[bs+1][2], s[bs+1][3]);
            uint32_t a20 = pack2(s[bs+2][0], s[bs+2][1]);
            uint32_t a21 = pack2(s[bs+2][2], s[bs+2][3]);
            uint32_t a30 = pack2(s[bs+3][0], s[bs+3][1]);
            uint32_t a31 = pack2(s[bs+3][2], s[bs+3][3]);
            #pragma unroll
            for (int nj = 0; nj < 8; nj++) {
                int n0 = nj * 8 + rr;
                uint4 fb = *(uint4*)&sVb[sl * 1024 + n0 * 16 + frot];
                mma16(o[nj], a00, a01, a10, a11, fb.x, fb.y);
                mma16(o[nj], a20, a21, a30, a31, fb.z, fb.w);
            }
        }
        __syncthreads();
    }

    float inv0 = 1.f / l0, inv1 = 1.f / l1;
    int t0 = qb * 128 + r0;
    #pragma unroll
    for (int ni = 0; ni < 8; ni++) {
        int dh = ni * 8 + 2 * q4;
        *(float2*)&O[((((size_t)b * Tc + t0) * Hc + h) * DHc) + dh] =
            make_float2(o[ni][0] * inv0, o[ni][1] * inv0);
        *(float2*)&O[((((size_t)b * Tc + t0 + 8) * Hc + h) * DHc) + dh] =
            make_float2(o[ni][2] * inv1, o[ni][3] * inv1);
    }
}

// ---------------- launch ----------------
extern "C" void kernel_launch(void* const* d_in, const int* in_sizes, int n_in,
                              void* d_out, int out_size)
{
    const float* x    = (const float*)d_in[0];
    const float* cosb = (const float*)d_in[1];
    const float* sinb = (const float*)d_in[2];
    const float* Wq  = (const float*)d_in[4];
    const float* bq  = (const float*)d_in[5];
    const float* Wk  = (const float*)d_in[6];
    const float* bk  = (const float*)d_in[7];
    const float* Wv  = (const float*)d_in[8];
    const float* bv  = (const float*)d_in[9];
    const float* Wo  = (const float*)d_in[10];
    const float* bo  = (const float*)d_in[11];
    const float* g1  = (const float*)d_in[12];
    const float* b1n = (const float*)d_in[13];
    const float* g2  = (const float*)d_in[14];
    const float* b2n = (const float*)d_in[15];
    const float* W1  = (const float*)d_in[16];
    const float* bf1 = (const float*)d_in[17];
    const float* W2  = (const float*)d_in[18];
    const float* bf2 = (const float*)d_in[19];
    float* out = (float*)d_out;

    float *h, *attn, *x2, *ffn;
    uint32_t *q, *k, *v;
    uint32_t *wq_t, *wk_t, *wv_t, *wo_t, *w1_t, *w2_t;
    cudaGetSymbolAddress((void**)&h,    g_h);
    cudaGetSymbolAddress((void**)&q,    g_q);
    cudaGetSymbolAddress((void**)&k,    g_k);
    cudaGetSymbolAddress((void**)&v,    g_v);
    cudaGetSymbolAddress((void**)&attn, g_attn);
    cudaGetSymbolAddress((void**)&x2,   g_x2);
    cudaGetSymbolAddress((void**)&ffn,  g_ffn);
    cudaGetSymbolAddress((void**)&wq_t, g_wq_t);
    cudaGetSymbolAddress((void**)&wk_t, g_wk_t);
    cudaGetSymbolAddress((void**)&wv_t, g_wv_t);
    cudaGetSymbolAddress((void**)&wo_t, g_wo_t);
    cudaGetSymbolAddress((void**)&w1_t, g_w1_t);
    cudaGetSymbolAddress((void**)&w2_t, g_w2_t);

    int attnSmem = 12288 * (int)sizeof(uint32_t);   // 49152 B
    cudaFuncSetAttribute(attn_tc, cudaFuncAttributeMaxDynamicSharedMemorySize, attnSmem);

    prep_all<<<3072, 256>>>(Wq, Wk, Wv, Wo, W1, W2,
                            wq_t, wk_t, wv_t, wo_t, w1_t, w2_t);

    dim3 blk(256);
    dim3 gProj(Dc / 128, ROWS / 128);        // (8, 32)
    dim3 gQkv(3 * Dc / 128, ROWS / 128);     // (24, 32)
    dim3 gFfn1(4 * Dc / 128, ROWS / 128);    // (32, 32)

    // 1. h = LN(x)
    ln_kernel<<<ROWS, blk>>>(x, g1, b1n, h);
    // 2. fused QKV projection + RoPE -> fp16 attention images
    gemm_qkv<<<gQkv, blk>>>(h, wq_t, wk_t, wv_t, bq, bk, bv, cosb, sinb, q, k, v);
    // 3. causal flash attention (fp16 images in, row-major fp32 out)
    dim3 gAttn(Tc / 128, Bc * Hc);
    attn_tc<<<gAttn, blk, attnSmem>>>(q, k, v, attn);
    // 4. x2 = x + attn @ Wo + bo
    gemm_tc<false><<<gProj, blk>>>(attn, wo_t, bo, x, x2, ROWS, Dc, Dc);
    // 5. h = LN(x2)
    ln_kernel<<<ROWS, blk>>>(x2, g2, b2n, h);
    // 6. ffn = gelu(h @ W1 + bf1)
    gemm_tc<true><<<gFfn1, blk>>>(h, w1_t, bf1, nullptr, ffn, ROWS, 4 * Dc, Dc);
    // 7. out = x2 + ffn @ W2 + bf2
    gemm_tc<false><<<gProj, blk>>>(ffn, w2_t, bf2, x2, out, ROWS, Dc, 4 * Dc);
}